// round 8
// baseline (speedup 1.0000x reference)
#include <cuda_runtime.h>
#include <cuda_bf16.h>
#include <math.h>
#include <stdint.h>

#define BB   8
#define CC   768
#define HH   56
#define LL   3136
#define NCAT 3840
#define QKV3 2304
#define EPSF 1e-6f
#define BN_EPSF 1e-5f

typedef __nv_bfloat16 bf16;

// ---------------------------------------------------------------------------
// Scratch (device globals; no allocations allowed)
// ---------------------------------------------------------------------------
static __device__ __align__(16) float g_pe[LL * 64];
static __device__ __align__(16) float g_pos[LL * CC];      // [l][c]
static __device__ __align__(16) float g_posT[CC * LL];     // [c][l]
static __device__ __align__(16) bf16  g_wcatb[CC * NCAT];  // [k][n]
static __device__ __align__(16) float g_bcat[NCAT];
static __device__ __align__(16) bf16  g_tb[(size_t)BB * LL * CC];
static __device__ __align__(16) bf16  g_qkv[(size_t)BB * LL * QKV3];
static __device__ __align__(16) bf16  g_qk1[(size_t)BB * LL * 1536];
static __device__ __align__(16) float g_pkv[BB * 16 * CC];
static __device__ __align__(16) float g_pks[BB * 16 * CC];
static __device__ __align__(16) float g_kv[BB * CC];
static __device__ __align__(16) float g_ks[BB * CC];
static __device__ __align__(16) bf16  g_resb[(size_t)BB * LL * CC];
static __device__ __align__(16) float g_mid[(size_t)BB * CC * CC];
static __device__ __align__(16) bf16  g_midb[(size_t)BB * CC * CC];

// ---------------------------------------------------------------------------
// PTX helpers (sm_100 baseline only — NO tcgen05)
// ---------------------------------------------------------------------------
__device__ __forceinline__ void mma_bf16(float* d, const uint32_t* a, const uint32_t* b) {
    asm volatile(
        "mma.sync.aligned.m16n8k16.row.col.f32.bf16.bf16.f32 "
        "{%0,%1,%2,%3}, {%4,%5,%6,%7}, {%8,%9}, {%0,%1,%2,%3};\n"
        : "+f"(d[0]), "+f"(d[1]), "+f"(d[2]), "+f"(d[3])
        : "r"(a[0]), "r"(a[1]), "r"(a[2]), "r"(a[3]), "r"(b[0]), "r"(b[1]));
}
__device__ __forceinline__ void ldsm_x4(uint32_t* r, uint32_t addr) {
    asm volatile("ldmatrix.sync.aligned.m8n8.x4.shared.b16 {%0,%1,%2,%3}, [%4];\n"
                 : "=r"(r[0]), "=r"(r[1]), "=r"(r[2]), "=r"(r[3]) : "r"(addr));
}
__device__ __forceinline__ void ldsm_x4t(uint32_t* r, uint32_t addr) {
    asm volatile("ldmatrix.sync.aligned.m8n8.x4.trans.shared.b16 {%0,%1,%2,%3}, [%4];\n"
                 : "=r"(r[0]), "=r"(r[1]), "=r"(r[2]), "=r"(r[3]) : "r"(addr));
}
__device__ __forceinline__ void cp16(void* s, const void* g, bool p) {
    uint32_t sa = (uint32_t)__cvta_generic_to_shared(s);
    int sz = p ? 16 : 0;
    asm volatile("cp.async.cg.shared.global [%0], [%1], 16, %2;\n" :: "r"(sa), "l"(g), "r"(sz));
}
__device__ __forceinline__ void cp_commit() { asm volatile("cp.async.commit_group;\n"); }
template <int N>
__device__ __forceinline__ void cp_wait() { asm volatile("cp.async.wait_group %0;\n" :: "n"(N)); }

// ---------------------------------------------------------------------------
// Reductions
// ---------------------------------------------------------------------------
__device__ __forceinline__ float block_sum256(float v) {
    __shared__ float sm[8];
    int lane = threadIdx.x & 31, w = threadIdx.x >> 5;
#pragma unroll
    for (int o = 16; o; o >>= 1) v += __shfl_xor_sync(0xffffffffu, v, o);
    if (lane == 0) sm[w] = v;
    __syncthreads();
    float t = sm[lane & 7];
#pragma unroll
    for (int o = 4; o; o >>= 1) t += __shfl_xor_sync(0xffffffffu, t, o);
    return t;
}
__device__ __forceinline__ float block_max256(float v) {
    __shared__ float sm[8];
    int lane = threadIdx.x & 31, w = threadIdx.x >> 5;
#pragma unroll
    for (int o = 16; o; o >>= 1) v = fmaxf(v, __shfl_xor_sync(0xffffffffu, v, o));
    if (lane == 0) sm[w] = v;
    __syncthreads();
    float t = sm[lane & 7];
#pragma unroll
    for (int o = 4; o; o >>= 1) t = fmaxf(t, __shfl_xor_sync(0xffffffffu, t, o));
    return t;
}

// ---------------------------------------------------------------------------
// Pre-kernels
// ---------------------------------------------------------------------------
__global__ void pe_kernel(void) {
    int idx = blockIdx.x * 256 + threadIdx.x;
    if (idx >= LL * 64) return;
    int l = idx >> 6, k = idx & 63;
    int kk = k & 31;
    float coord = (k < 32) ? (float)(l / HH + 1) : (float)(l % HH + 1);
    float v = coord / ((float)HH + EPSF) * 6.283185307179586f;
    float dt = powf(10000.0f, (float)(kk & ~1) / 32.0f);
    float p = v / dt;
    g_pe[idx] = (kk & 1) ? cosf(p) : sinf(p);
}

__global__ __launch_bounds__(256) void pos_kernel(const float* __restrict__ pw,
                                                  const float* __restrict__ pb) {
    __shared__ float pe_s[64];
    int l = blockIdx.x, tid = threadIdx.x;
    if (tid < 64) pe_s[tid] = g_pe[l * 64 + tid];
    __syncthreads();
#pragma unroll
    for (int j = 0; j < 3; j++) {
        int c = tid + j * 256;
        float acc = pb[c];
#pragma unroll 16
        for (int k = 0; k < 64; k++) acc += pe_s[k] * pw[k * CC + c];
        g_pos[(size_t)l * CC + c] = acc;
    }
}

// posT[c][l] = pos[l][c]
__global__ __launch_bounds__(256) void posT_kernel(void) {
    __shared__ float tile[32][33];
    int tx = threadIdx.x & 31, ty = threadIdx.x >> 5;
    int l0 = blockIdx.x * 32, c0 = blockIdx.y * 32;
#pragma unroll
    for (int i = 0; i < 4; i++)
        tile[ty + i * 8][tx] = g_pos[(size_t)(l0 + ty + i * 8) * CC + c0 + tx];
    __syncthreads();
#pragma unroll
    for (int i = 0; i < 4; i++)
        g_posT[(size_t)(c0 + ty + i * 8) * LL + l0 + tx] = tile[tx][ty + i * 8];
}

// Weights -> bf16 [k][n], biases fp32
__global__ void wcat_kernel(const float* __restrict__ wq, const float* __restrict__ wk,
                            const float* __restrict__ wv, const float* __restrict__ wq1,
                            const float* __restrict__ wk1,
                            const float* __restrict__ bq, const float* __restrict__ bk,
                            const float* __restrict__ bv, const float* __restrict__ bq1,
                            const float* __restrict__ bk1) {
    int idx = blockIdx.x * 256 + threadIdx.x;
    if (idx < NCAT) {
        int g = idx / CC, c = idx % CC;
        const float* bp = (g == 0) ? bq : (g == 1) ? bk : (g == 2) ? bv : (g == 3) ? bq1 : bk1;
        g_bcat[idx] = bp[c];
    }
    if (idx >= CC * NCAT) return;
    int k = idx / NCAT, n = idx % NCAT;
    int g = n / CC, c = n % CC;
    const float* wp = (g == 0) ? wq : (g == 1) ? wk : (g == 2) ? wv : (g == 3) ? wq1 : wk1;
    g_wcatb[idx] = __float2bfloat16_rn(wp[k * CC + c]);
}

// t_bf16[b,l,c] = bf16(x[b,c,l] + pos[l,c])
__global__ __launch_bounds__(256) void addpos_kernel(const float* __restrict__ x) {
    __shared__ float tile[32][33];
    int tx = threadIdx.x & 31, ty = threadIdx.x >> 5;
    int l0 = blockIdx.x * 32, c0 = blockIdx.y * 32, b = blockIdx.z;
#pragma unroll
    for (int i = 0; i < 4; i++) {
        int c = c0 + ty + i * 8;
        tile[ty + i * 8][tx] = x[(size_t)(b * CC + c) * LL + l0 + tx];
    }
    __syncthreads();
#pragma unroll
    for (int i = 0; i < 4; i++) {
        int l = l0 + ty + i * 8;
        int c = c0 + tx;
        g_tb[((size_t)b * LL + l) * CC + c] =
            __float2bfloat16_rn(tile[tx][ty + i * 8] + g_pos[(size_t)l * CC + c]);
    }
}

// ---------------------------------------------------------------------------
// bf16 tensor-core GEMM. BM=BN=128, BK=32, 256 threads, warp tile 32x64.
// MODE 0: fp32 C store (gemm2).
// MODE 1: projection epilogue — +bias, ReLU n<1536; bf16 out to qkv/qk1 (gemm1).
// MODE 2: fused final — y = relu(BN(x + posT + gamma*acc)), NCHW store (gemm3).
// ---------------------------------------------------------------------------
template <bool TRANSA, int MODE>
__global__ __launch_bounds__(256) void gemm_bf(
    const bf16* __restrict__ A, int lda, size_t sA,
    const bf16* __restrict__ B, int ldb, size_t sB,
    float* __restrict__ C, int ldc, size_t sC, int M, int K,
    const float* __restrict__ bias, bf16* __restrict__ O1, bf16* __restrict__ O2,
    const float* __restrict__ x, const float* __restrict__ posT,
    const float* __restrict__ gamma,
    const float* __restrict__ bw, const float* __restrict__ bbv,
    const float* __restrict__ mean, const float* __restrict__ var,
    float* __restrict__ out)
{
    constexpr int ASZ = TRANSA ? 32 * 136 : 128 * 40;
    __shared__ __align__(16) bf16 As[2][ASZ];
    __shared__ __align__(16) bf16 Bs[2][32 * 136];

    A += (size_t)blockIdx.z * sA;
    B += (size_t)blockIdx.z * sB;
    if (MODE == 0) C += (size_t)blockIdx.z * sC;

    const int tid = threadIdx.x;
    const int m0 = blockIdx.y * 128, n0 = blockIdx.x * 128;
    const int lane = tid & 31, wid = tid >> 5;
    const int wm = wid >> 1, wn = wid & 1;
    const int tg = lane >> 2, tig = lane & 3;

    auto load_tiles = [&](int buf, int kb) {
#pragma unroll
        for (int i = 0; i < 2; i++) {
            int f = tid + i * 256;
            if (!TRANSA) {
                int row = f >> 2, c8 = (f & 3) << 3;
                bool p = (m0 + row) < M;
                const bf16* g = A + (size_t)(p ? (m0 + row) : 0) * lda + kb + c8;
                cp16(&As[buf][row * 40 + c8], g, p);
            } else {
                int row = f >> 4, c8 = (f & 15) << 3;
                const bf16* g = A + (size_t)(kb + row) * lda + m0 + c8;
                cp16(&As[buf][row * 136 + c8], g, true);
            }
        }
#pragma unroll
        for (int i = 0; i < 2; i++) {
            int f = tid + i * 256;
            int row = f >> 4, c8 = (f & 15) << 3;
            const bf16* g = B + (size_t)(kb + row) * ldb + n0 + c8;
            cp16(&Bs[buf][row * 136 + c8], g, true);
        }
        cp_commit();
    };

    float acc[2][8][4];
#pragma unroll
    for (int mi = 0; mi < 2; mi++)
#pragma unroll
        for (int ni = 0; ni < 8; ni++)
#pragma unroll
            for (int r = 0; r < 4; r++) acc[mi][ni][r] = 0.0f;

    int a_off[2], b_off;
    if (!TRANSA) {
#pragma unroll
        for (int mi = 0; mi < 2; mi++)
            a_off[mi] = (wm * 32 + mi * 16 + (lane & 15)) * 40 + ((lane >> 4) << 3);
    } else {
#pragma unroll
        for (int mi = 0; mi < 2; mi++)
            a_off[mi] = (((lane >> 4) & 1) * 8 + (lane & 7)) * 136
                        + wm * 32 + mi * 16 + ((lane >> 3) & 1) * 8;
    }
    b_off = (((lane >> 3) & 1) * 8 + (lane & 7)) * 136
            + wn * 64 + ((lane >> 4) & 1) * 8;

    const int nk = K >> 5;
    load_tiles(0, 0);

    for (int it = 0; it < nk; it++) {
        if (it + 1 < nk) { load_tiles((it + 1) & 1, (it + 1) << 5); cp_wait<1>(); }
        else             { cp_wait<0>(); }
        __syncthreads();

        uint32_t abase = (uint32_t)__cvta_generic_to_shared(As[it & 1]);
        uint32_t bbase = (uint32_t)__cvta_generic_to_shared(Bs[it & 1]);
#pragma unroll
        for (int kk = 0; kk < 32; kk += 16) {
            uint32_t af[2][4];
#pragma unroll
            for (int mi = 0; mi < 2; mi++) {
                uint32_t ad;
                if (!TRANSA) ad = abase + (uint32_t)(a_off[mi] + kk) * 2;
                else         ad = abase + (uint32_t)(a_off[mi] + kk * 136) * 2;
                if (!TRANSA) ldsm_x4(af[mi], ad);
                else         ldsm_x4t(af[mi], ad);
            }
            uint32_t bfr[8][2];
#pragma unroll
            for (int ni2 = 0; ni2 < 4; ni2++) {
                uint32_t r[4];
                uint32_t bd = bbase + (uint32_t)(b_off + kk * 136 + ni2 * 16) * 2;
                ldsm_x4t(r, bd);
                bfr[2 * ni2][0] = r[0]; bfr[2 * ni2][1] = r[1];
                bfr[2 * ni2 + 1][0] = r[2]; bfr[2 * ni2 + 1][1] = r[3];
            }
#pragma unroll
            for (int mi = 0; mi < 2; mi++)
#pragma unroll
                for (int ni = 0; ni < 8; ni++)
                    mma_bf16(acc[mi][ni], af[mi], bfr[ni]);
        }
        __syncthreads();
    }

    if (MODE == 0) {
#pragma unroll
        for (int mi = 0; mi < 2; mi++) {
            int r0 = m0 + wm * 32 + mi * 16 + tg;
#pragma unroll
            for (int ni = 0; ni < 8; ni++) {
                int c0 = n0 + wn * 64 + ni * 8 + (tig << 1);
                if (r0 < M)
                    *(float2*)(C + (size_t)r0 * ldc + c0) =
                        make_float2(acc[mi][ni][0], acc[mi][ni][1]);
                if (r0 + 8 < M)
                    *(float2*)(C + (size_t)(r0 + 8) * ldc + c0) =
                        make_float2(acc[mi][ni][2], acc[mi][ni][3]);
            }
        }
    } else if (MODE == 1) {
#pragma unroll
        for (int mi = 0; mi < 2; mi++) {
            int r0 = m0 + wm * 32 + mi * 16 + tg;
#pragma unroll
            for (int ni = 0; ni < 8; ni++) {
                int c0 = n0 + wn * 64 + ni * 8 + (tig << 1);
                float2 bb = *(const float2*)(bias + c0);
                float v0 = acc[mi][ni][0] + bb.x, v1 = acc[mi][ni][1] + bb.y;
                float v2 = acc[mi][ni][2] + bb.x, v3 = acc[mi][ni][3] + bb.y;
                if (c0 < 1536) {
                    v0 = fmaxf(v0, 0.f); v1 = fmaxf(v1, 0.f);
                    v2 = fmaxf(v2, 0.f); v3 = fmaxf(v3, 0.f);
                }
                __nv_bfloat162 p01 = __floats2bfloat162_rn(v0, v1);
                __nv_bfloat162 p23 = __floats2bfloat162_rn(v2, v3);
                if (c0 < QKV3) {
                    *(__nv_bfloat162*)(O1 + (size_t)r0 * QKV3 + c0) = p01;
                    *(__nv_bfloat162*)(O1 + (size_t)(r0 + 8) * QKV3 + c0) = p23;
                } else {
                    int cq = c0 - QKV3;
                    *(__nv_bfloat162*)(O2 + (size_t)r0 * 1536 + cq) = p01;
                    *(__nv_bfloat162*)(O2 + (size_t)(r0 + 8) * 1536 + cq) = p23;
                }
            }
        }
    } else {
        // MODE 2: fused final. Stage gm*acc through smem in 32-col chunks,
        // then coalesced NCHW epilogue.
        float* tbuf = reinterpret_cast<float*>(&As[0][0]);   // 32 x 132 fp32
        const float gm = gamma[0];
        const int bz = blockIdx.z;
#pragma unroll
        for (int ci = 0; ci < 4; ci++) {
            __syncthreads();
            if (wn == (ci >> 1)) {
                int nlo = (ci & 1) * 4;
#pragma unroll
                for (int mi = 0; mi < 2; mi++) {
                    int l0 = wm * 32 + mi * 16 + tg;
#pragma unroll
                    for (int nj = 0; nj < 4; nj++) {
                        int ni = nlo + nj;
                        int cl = wn * 64 + ni * 8 + (tig << 1) - ci * 32;
                        tbuf[cl * 132 + l0]           = gm * acc[mi][ni][0];
                        tbuf[(cl + 1) * 132 + l0]     = gm * acc[mi][ni][1];
                        tbuf[cl * 132 + l0 + 8]       = gm * acc[mi][ni][2];
                        tbuf[(cl + 1) * 132 + l0 + 8] = gm * acc[mi][ni][3];
                    }
                }
            }
            __syncthreads();
            int cl = tid >> 3;
            int lbase = (tid & 7) * 16;
            if (m0 + lbase < M) {
                int c = n0 + ci * 32 + cl;
                float ibn = rsqrtf(var[c] + BN_EPSF) * bw[c];
                float mb = mean[c], b2 = bbv[c];
                const float* xrow = x + ((size_t)bz * CC + c) * LL + m0 + lbase;
                const float* prow = posT + (size_t)c * LL + m0 + lbase;
                float* orow = out + ((size_t)bz * CC + c) * LL + m0 + lbase;
#pragma unroll
                for (int i = 0; i < 16; i++) {
                    float v = xrow[i] + prow[i] + tbuf[cl * 132 + lbase + i];
                    v = (v - mb) * ibn + b2;
                    orow[i] = fmaxf(v, 0.f);
                }
            }
        }
    }
}

// ---------------------------------------------------------------------------
// kv_diag / K.sum (bf16 inputs)
// ---------------------------------------------------------------------------
__global__ __launch_bounds__(256) void kvks_partial(void) {
    int c = blockIdx.x * 256 + threadIdx.x;
    int seg = blockIdx.y, b = blockIdx.z;
    const bf16* base = g_qkv + ((size_t)b * LL + seg * 196) * QKV3;
    float skv = 0.f, sks = 0.f;
#pragma unroll 4
    for (int l = 0; l < 196; l++) {
        float kk = __bfloat162float(base[(size_t)l * QKV3 + CC + c]);
        float vv = __bfloat162float(base[(size_t)l * QKV3 + 2 * CC + c]);
        skv += kk * vv;
        sks += kk;
    }
    g_pkv[(b * 16 + seg) * CC + c] = skv;
    g_pks[(b * 16 + seg) * CC + c] = sks;
}

__global__ void kvks_reduce(void) {
    int i = blockIdx.x * 256 + threadIdx.x;
    if (i >= BB * CC) return;
    int b = i / CC, c = i % CC;
    float skv = 0.f, sks = 0.f;
#pragma unroll
    for (int s = 0; s < 16; s++) {
        skv += g_pkv[(b * 16 + s) * CC + c];
        sks += g_pks[(b * 16 + s) * CC + c];
    }
    g_kv[i] = skv;
    g_ks[i] = sks;
}

__global__ __launch_bounds__(256) void zres_kernel(void) {
    int bl = blockIdx.x;
    int b = bl / LL;
    int tid = threadIdx.x;
    const bf16* qrow = g_qkv + (size_t)bl * QKV3;
    float q0 = __bfloat162float(qrow[tid]);
    float q1 = __bfloat162float(qrow[tid + 256]);
    float q2 = __bfloat162float(qrow[tid + 512]);
    const float* ks = g_ks + b * CC;
    float p = q0 * (ks[tid] + EPSF) + q1 * (ks[tid + 256] + EPSF) + q2 * (ks[tid + 512] + EPSF);
    float tot = block_sum256(p);
    float z = 1.0f / tot;
    const float* kv = g_kv + b * CC;
    bf16* outp = g_resb + (size_t)bl * CC;
    outp[tid]       = __float2bfloat16_rn(q0 * kv[tid] * z);
    outp[tid + 256] = __float2bfloat16_rn(q1 * kv[tid + 256] * z);
    outp[tid + 512] = __float2bfloat16_rn(q2 * kv[tid + 512] * z);
}

__global__ __launch_bounds__(256) void softmax_kernel(void) {
    const float* row = g_mid + (size_t)blockIdx.x * CC;
    bf16* rowo = g_midb + (size_t)blockIdx.x * CC;
    int tid = threadIdx.x;
    float v0 = row[tid], v1 = row[tid + 256], v2 = row[tid + 512];
    float m = block_max256(fmaxf(v0, fmaxf(v1, v2)));
    __syncthreads();
    float e0 = expf(v0 - m), e1 = expf(v1 - m), e2 = expf(v2 - m);
    float s = block_sum256(e0 + e1 + e2);
    float inv = 1.0f / s;
    rowo[tid]       = __float2bfloat16_rn(e0 * inv);
    rowo[tid + 256] = __float2bfloat16_rn(e1 * inv);
    rowo[tid + 512] = __float2bfloat16_rn(e2 * inv);
}

// ---------------------------------------------------------------------------
// Launch
// ---------------------------------------------------------------------------
extern "C" void kernel_launch(void* const* d_in, const int* in_sizes, int n_in,
                              void* d_out, int out_size) {
    const float* x    = (const float*)d_in[0];
    const float* wq   = (const float*)d_in[1];
    const float* bq   = (const float*)d_in[2];
    const float* wk   = (const float*)d_in[3];
    const float* bk   = (const float*)d_in[4];
    const float* wv   = (const float*)d_in[5];
    const float* bv   = (const float*)d_in[6];
    const float* wq1  = (const float*)d_in[7];
    const float* bq1  = (const float*)d_in[8];
    const float* wk1  = (const float*)d_in[9];
    const float* bk1  = (const float*)d_in[10];
    const float* gam  = (const float*)d_in[11];
    const float* bn_w = (const float*)d_in[12];
    const float* bn_b = (const float*)d_in[13];
    const float* bn_m = (const float*)d_in[14];
    const float* bn_v = (const float*)d_in[15];
    const float* pw   = (const float*)d_in[16];
    const float* pb   = (const float*)d_in[17];
    float* out = (float*)d_out;

    float *p_bcat, *p_mid, *p_posT;
    bf16 *p_tb, *p_wcatb, *p_qkv, *p_qk1, *p_resb, *p_midb;
    cudaGetSymbolAddress((void**)&p_bcat,  g_bcat);
    cudaGetSymbolAddress((void**)&p_mid,   g_mid);
    cudaGetSymbolAddress((void**)&p_posT,  g_posT);
    cudaGetSymbolAddress((void**)&p_tb,    g_tb);
    cudaGetSymbolAddress((void**)&p_wcatb, g_wcatb);
    cudaGetSymbolAddress((void**)&p_qkv,   g_qkv);
    cudaGetSymbolAddress((void**)&p_qk1,   g_qk1);
    cudaGetSymbolAddress((void**)&p_resb,  g_resb);
    cudaGetSymbolAddress((void**)&p_midb,  g_midb);

    pe_kernel<<<(LL * 64 + 255) / 256, 256>>>();
    pos_kernel<<<LL, 256>>>(pw, pb);
    posT_kernel<<<dim3(LL / 32, CC / 32), 256>>>();
    wcat_kernel<<<(CC * NCAT + 255) / 256, 256>>>(wq, wk, wv, wq1, wk1,
                                                  bq, bk, bv, bq1, bk1);
    addpos_kernel<<<dim3(LL / 32, CC / 32, BB), 256>>>(x);

    // gemm1: projection, bf16 epilogue split Q,K,V / Q1,K1
    gemm_bf<false, 1><<<dim3(NCAT / 128, (BB * LL) / 128, 1), 256>>>(
        p_tb, CC, 0, p_wcatb, NCAT, 0,
        nullptr, 0, 0, BB * LL, CC,
        p_bcat, p_qkv, p_qk1,
        nullptr, nullptr, nullptr, nullptr, nullptr, nullptr, nullptr, nullptr);

    kvks_partial<<<dim3(CC / 256, 16, BB), 256>>>();
    kvks_reduce<<<(BB * CC + 255) / 256, 256>>>();
    zres_kernel<<<BB * LL, 256>>>();

    // gemm2: mid = Q1^T @ K1 per batch
    gemm_bf<true, 0><<<dim3(CC / 128, CC / 128, BB), 256>>>(
        p_qk1, 1536, (size_t)LL * 1536,
        p_qk1 + 768, 1536, (size_t)LL * 1536,
        p_mid, CC, (size_t)CC * CC, CC, LL,
        nullptr, nullptr, nullptr,
        nullptr, nullptr, nullptr, nullptr, nullptr, nullptr, nullptr, nullptr);

    softmax_kernel<<<BB * CC, 256>>>();

    // gemm3 fused with BN/ReLU/transpose final
    gemm_bf<false, 2><<<dim3(CC / 128, (LL + 127) / 128, BB), 256>>>(
        p_resb, CC, (size_t)LL * CC,
        p_midb, CC, (size_t)CC * CC,
        nullptr, 0, 0, LL, CC,
        nullptr, nullptr, nullptr,
        x, p_posT, gam, bn_w, bn_b, bn_m, bn_v, out);
}

// round 9
// speedup vs baseline: 1.0630x; 1.0630x over previous
#include <cuda_runtime.h>
#include <cuda_bf16.h>
#include <math.h>
#include <stdint.h>

#define BB   8
#define CC   768
#define HH   56
#define LL   3136
#define NCAT 3840
#define QKV3 2304
#define EPSF 1e-6f
#define BN_EPSF 1e-5f

typedef __nv_bfloat16 bf16;

// ---------------------------------------------------------------------------
// Scratch (device globals; no allocations allowed)
// ---------------------------------------------------------------------------
static __device__ __align__(16) float g_pe[LL * 64];
static __device__ __align__(16) float g_pos[LL * CC];      // [l][c]
static __device__ __align__(16) float g_posT[CC * LL];     // [c][l]
static __device__ __align__(16) bf16  g_wcatb[CC * NCAT];  // [k][n]
static __device__ __align__(16) float g_bcat[NCAT];
static __device__ __align__(16) bf16  g_tb[(size_t)BB * LL * CC];
static __device__ __align__(16) bf16  g_qkv[(size_t)BB * LL * QKV3];
static __device__ __align__(16) bf16  g_qk1[(size_t)BB * LL * 1536];
static __device__ __align__(16) float g_pkv[BB * 16 * CC];
static __device__ __align__(16) float g_pks[BB * 16 * CC];
static __device__ __align__(16) float g_kv[BB * CC];
static __device__ __align__(16) float g_ks[BB * CC];
static __device__ __align__(16) bf16  g_resb[(size_t)BB * LL * CC];
static __device__ __align__(16) float g_mid[(size_t)BB * CC * CC];
static __device__ __align__(16) bf16  g_midb[(size_t)BB * CC * CC];
static __device__ __align__(16) bf16  g_res2b[(size_t)BB * LL * CC];

// ---------------------------------------------------------------------------
// PTX helpers (sm_100 baseline only — NO tcgen05)
// ---------------------------------------------------------------------------
__device__ __forceinline__ void mma_bf16(float* d, const uint32_t* a, const uint32_t* b) {
    asm volatile(
        "mma.sync.aligned.m16n8k16.row.col.f32.bf16.bf16.f32 "
        "{%0,%1,%2,%3}, {%4,%5,%6,%7}, {%8,%9}, {%0,%1,%2,%3};\n"
        : "+f"(d[0]), "+f"(d[1]), "+f"(d[2]), "+f"(d[3])
        : "r"(a[0]), "r"(a[1]), "r"(a[2]), "r"(a[3]), "r"(b[0]), "r"(b[1]));
}
__device__ __forceinline__ void ldsm_x4(uint32_t* r, uint32_t addr) {
    asm volatile("ldmatrix.sync.aligned.m8n8.x4.shared.b16 {%0,%1,%2,%3}, [%4];\n"
                 : "=r"(r[0]), "=r"(r[1]), "=r"(r[2]), "=r"(r[3]) : "r"(addr));
}
__device__ __forceinline__ void ldsm_x4t(uint32_t* r, uint32_t addr) {
    asm volatile("ldmatrix.sync.aligned.m8n8.x4.trans.shared.b16 {%0,%1,%2,%3}, [%4];\n"
                 : "=r"(r[0]), "=r"(r[1]), "=r"(r[2]), "=r"(r[3]) : "r"(addr));
}
__device__ __forceinline__ void cp16(void* s, const void* g, bool p) {
    uint32_t sa = (uint32_t)__cvta_generic_to_shared(s);
    int sz = p ? 16 : 0;
    asm volatile("cp.async.cg.shared.global [%0], [%1], 16, %2;\n" :: "r"(sa), "l"(g), "r"(sz));
}
__device__ __forceinline__ void cp_commit() { asm volatile("cp.async.commit_group;\n"); }
template <int N>
__device__ __forceinline__ void cp_wait() { asm volatile("cp.async.wait_group %0;\n" :: "n"(N)); }

// ---------------------------------------------------------------------------
// Reductions
// ---------------------------------------------------------------------------
__device__ __forceinline__ float block_sum256(float v) {
    __shared__ float sm[8];
    int lane = threadIdx.x & 31, w = threadIdx.x >> 5;
#pragma unroll
    for (int o = 16; o; o >>= 1) v += __shfl_xor_sync(0xffffffffu, v, o);
    if (lane == 0) sm[w] = v;
    __syncthreads();
    float t = sm[lane & 7];
#pragma unroll
    for (int o = 4; o; o >>= 1) t += __shfl_xor_sync(0xffffffffu, t, o);
    return t;
}
__device__ __forceinline__ float block_max256(float v) {
    __shared__ float sm[8];
    int lane = threadIdx.x & 31, w = threadIdx.x >> 5;
#pragma unroll
    for (int o = 16; o; o >>= 1) v = fmaxf(v, __shfl_xor_sync(0xffffffffu, v, o));
    if (lane == 0) sm[w] = v;
    __syncthreads();
    float t = sm[lane & 7];
#pragma unroll
    for (int o = 4; o; o >>= 1) t = fmaxf(t, __shfl_xor_sync(0xffffffffu, t, o));
    return t;
}

// ---------------------------------------------------------------------------
// Pre-kernels
// ---------------------------------------------------------------------------
__global__ void pe_kernel(void) {
    int idx = blockIdx.x * 256 + threadIdx.x;
    if (idx >= LL * 64) return;
    int l = idx >> 6, k = idx & 63;
    int kk = k & 31;
    float coord = (k < 32) ? (float)(l / HH + 1) : (float)(l % HH + 1);
    float v = coord / ((float)HH + EPSF) * 6.283185307179586f;
    float dt = powf(10000.0f, (float)(kk & ~1) / 32.0f);
    float p = v / dt;
    g_pe[idx] = (kk & 1) ? cosf(p) : sinf(p);
}

__global__ __launch_bounds__(256) void pos_kernel(const float* __restrict__ pw,
                                                  const float* __restrict__ pb) {
    __shared__ float pe_s[64];
    int l = blockIdx.x, tid = threadIdx.x;
    if (tid < 64) pe_s[tid] = g_pe[l * 64 + tid];
    __syncthreads();
#pragma unroll
    for (int j = 0; j < 3; j++) {
        int c = tid + j * 256;
        float acc = pb[c];
#pragma unroll 16
        for (int k = 0; k < 64; k++) acc += pe_s[k] * pw[k * CC + c];
        g_pos[(size_t)l * CC + c] = acc;
    }
}

// posT[c][l] = pos[l][c]
__global__ __launch_bounds__(256) void posT_kernel(void) {
    __shared__ float tile[32][33];
    int tx = threadIdx.x & 31, ty = threadIdx.x >> 5;
    int l0 = blockIdx.x * 32, c0 = blockIdx.y * 32;
#pragma unroll
    for (int i = 0; i < 4; i++)
        tile[ty + i * 8][tx] = g_pos[(size_t)(l0 + ty + i * 8) * CC + c0 + tx];
    __syncthreads();
#pragma unroll
    for (int i = 0; i < 4; i++)
        g_posT[(size_t)(c0 + ty + i * 8) * LL + l0 + tx] = tile[tx][ty + i * 8];
}

// Weights -> bf16 [k][n], biases fp32
__global__ void wcat_kernel(const float* __restrict__ wq, const float* __restrict__ wk,
                            const float* __restrict__ wv, const float* __restrict__ wq1,
                            const float* __restrict__ wk1,
                            const float* __restrict__ bq, const float* __restrict__ bk,
                            const float* __restrict__ bv, const float* __restrict__ bq1,
                            const float* __restrict__ bk1) {
    int idx = blockIdx.x * 256 + threadIdx.x;
    if (idx < NCAT) {
        int g = idx / CC, c = idx % CC;
        const float* bp = (g == 0) ? bq : (g == 1) ? bk : (g == 2) ? bv : (g == 3) ? bq1 : bk1;
        g_bcat[idx] = bp[c];
    }
    if (idx >= CC * NCAT) return;
    int k = idx / NCAT, n = idx % NCAT;
    int g = n / CC, c = n % CC;
    const float* wp = (g == 0) ? wq : (g == 1) ? wk : (g == 2) ? wv : (g == 3) ? wq1 : wk1;
    g_wcatb[idx] = __float2bfloat16_rn(wp[k * CC + c]);
}

// t_bf16[b,l,c] = bf16(x[b,c,l] + pos[l,c])
__global__ __launch_bounds__(256) void addpos_kernel(const float* __restrict__ x) {
    __shared__ float tile[32][33];
    int tx = threadIdx.x & 31, ty = threadIdx.x >> 5;
    int l0 = blockIdx.x * 32, c0 = blockIdx.y * 32, b = blockIdx.z;
#pragma unroll
    for (int i = 0; i < 4; i++) {
        int c = c0 + ty + i * 8;
        tile[ty + i * 8][tx] = x[(size_t)(b * CC + c) * LL + l0 + tx];
    }
    __syncthreads();
#pragma unroll
    for (int i = 0; i < 4; i++) {
        int l = l0 + ty + i * 8;
        int c = c0 + tx;
        g_tb[((size_t)b * LL + l) * CC + c] =
            __float2bfloat16_rn(tile[tx][ty + i * 8] + g_pos[(size_t)l * CC + c]);
    }
}

// ---------------------------------------------------------------------------
// bf16 tensor-core GEMM. BM=BN=128, BK=32, 256 threads, warp tile 32x64.
// MODE 0: fp32 C store (gemm2).
// MODE 1: projection epilogue — +bias, ReLU n<1536; bf16 to qkv/qk1 (gemm1).
// MODE 3: plain bf16 store to O1, ld = ldc (gemm3 -> res2 bf16).
// ---------------------------------------------------------------------------
template <bool TRANSA, int MODE>
__global__ __launch_bounds__(256) void gemm_bf(
    const bf16* __restrict__ A, int lda, size_t sA,
    const bf16* __restrict__ B, int ldb, size_t sB,
    float* __restrict__ C, int ldc, size_t sC, int M, int K,
    const float* __restrict__ bias, bf16* __restrict__ O1, bf16* __restrict__ O2)
{
    constexpr int ASZ = TRANSA ? 32 * 136 : 128 * 40;
    __shared__ __align__(16) bf16 As[2][ASZ];
    __shared__ __align__(16) bf16 Bs[2][32 * 136];

    A += (size_t)blockIdx.z * sA;
    B += (size_t)blockIdx.z * sB;
    if (MODE == 0) C += (size_t)blockIdx.z * sC;
    if (MODE == 3) O1 += (size_t)blockIdx.z * sC;

    const int tid = threadIdx.x;
    const int m0 = blockIdx.y * 128, n0 = blockIdx.x * 128;
    const int lane = tid & 31, wid = tid >> 5;
    const int wm = wid >> 1, wn = wid & 1;
    const int tg = lane >> 2, tig = lane & 3;

    auto load_tiles = [&](int buf, int kb) {
#pragma unroll
        for (int i = 0; i < 2; i++) {
            int f = tid + i * 256;
            if (!TRANSA) {
                int row = f >> 2, c8 = (f & 3) << 3;
                bool p = (m0 + row) < M;
                const bf16* g = A + (size_t)(p ? (m0 + row) : 0) * lda + kb + c8;
                cp16(&As[buf][row * 40 + c8], g, p);
            } else {
                int row = f >> 4, c8 = (f & 15) << 3;
                const bf16* g = A + (size_t)(kb + row) * lda + m0 + c8;
                cp16(&As[buf][row * 136 + c8], g, true);
            }
        }
#pragma unroll
        for (int i = 0; i < 2; i++) {
            int f = tid + i * 256;
            int row = f >> 4, c8 = (f & 15) << 3;
            const bf16* g = B + (size_t)(kb + row) * ldb + n0 + c8;
            cp16(&Bs[buf][row * 136 + c8], g, true);
        }
        cp_commit();
    };

    float acc[2][8][4];
#pragma unroll
    for (int mi = 0; mi < 2; mi++)
#pragma unroll
        for (int ni = 0; ni < 8; ni++)
#pragma unroll
            for (int r = 0; r < 4; r++) acc[mi][ni][r] = 0.0f;

    int a_off[2], b_off;
    if (!TRANSA) {
#pragma unroll
        for (int mi = 0; mi < 2; mi++)
            a_off[mi] = (wm * 32 + mi * 16 + (lane & 15)) * 40 + ((lane >> 4) << 3);
    } else {
#pragma unroll
        for (int mi = 0; mi < 2; mi++)
            a_off[mi] = (((lane >> 4) & 1) * 8 + (lane & 7)) * 136
                        + wm * 32 + mi * 16 + ((lane >> 3) & 1) * 8;
    }
    b_off = (((lane >> 3) & 1) * 8 + (lane & 7)) * 136
            + wn * 64 + ((lane >> 4) & 1) * 8;

    const int nk = K >> 5;
    load_tiles(0, 0);

    for (int it = 0; it < nk; it++) {
        if (it + 1 < nk) { load_tiles((it + 1) & 1, (it + 1) << 5); cp_wait<1>(); }
        else             { cp_wait<0>(); }
        __syncthreads();

        uint32_t abase = (uint32_t)__cvta_generic_to_shared(As[it & 1]);
        uint32_t bbase = (uint32_t)__cvta_generic_to_shared(Bs[it & 1]);
#pragma unroll
        for (int kk = 0; kk < 32; kk += 16) {
            uint32_t af[2][4];
#pragma unroll
            for (int mi = 0; mi < 2; mi++) {
                uint32_t ad;
                if (!TRANSA) ad = abase + (uint32_t)(a_off[mi] + kk) * 2;
                else         ad = abase + (uint32_t)(a_off[mi] + kk * 136) * 2;
                if (!TRANSA) ldsm_x4(af[mi], ad);
                else         ldsm_x4t(af[mi], ad);
            }
            uint32_t bfr[8][2];
#pragma unroll
            for (int ni2 = 0; ni2 < 4; ni2++) {
                uint32_t r[4];
                uint32_t bd = bbase + (uint32_t)(b_off + kk * 136 + ni2 * 16) * 2;
                ldsm_x4t(r, bd);
                bfr[2 * ni2][0] = r[0]; bfr[2 * ni2][1] = r[1];
                bfr[2 * ni2 + 1][0] = r[2]; bfr[2 * ni2 + 1][1] = r[3];
            }
#pragma unroll
            for (int mi = 0; mi < 2; mi++)
#pragma unroll
                for (int ni = 0; ni < 8; ni++)
                    mma_bf16(acc[mi][ni], af[mi], bfr[ni]);
        }
        __syncthreads();
    }

    if (MODE == 0) {
#pragma unroll
        for (int mi = 0; mi < 2; mi++) {
            int r0 = m0 + wm * 32 + mi * 16 + tg;
#pragma unroll
            for (int ni = 0; ni < 8; ni++) {
                int c0 = n0 + wn * 64 + ni * 8 + (tig << 1);
                if (r0 < M)
                    *(float2*)(C + (size_t)r0 * ldc + c0) =
                        make_float2(acc[mi][ni][0], acc[mi][ni][1]);
                if (r0 + 8 < M)
                    *(float2*)(C + (size_t)(r0 + 8) * ldc + c0) =
                        make_float2(acc[mi][ni][2], acc[mi][ni][3]);
            }
        }
    } else if (MODE == 1) {
#pragma unroll
        for (int mi = 0; mi < 2; mi++) {
            int r0 = m0 + wm * 32 + mi * 16 + tg;
#pragma unroll
            for (int ni = 0; ni < 8; ni++) {
                int c0 = n0 + wn * 64 + ni * 8 + (tig << 1);
                float2 bb = *(const float2*)(bias + c0);
                float v0 = acc[mi][ni][0] + bb.x, v1 = acc[mi][ni][1] + bb.y;
                float v2 = acc[mi][ni][2] + bb.x, v3 = acc[mi][ni][3] + bb.y;
                if (c0 < 1536) {
                    v0 = fmaxf(v0, 0.f); v1 = fmaxf(v1, 0.f);
                    v2 = fmaxf(v2, 0.f); v3 = fmaxf(v3, 0.f);
                }
                __nv_bfloat162 p01 = __floats2bfloat162_rn(v0, v1);
                __nv_bfloat162 p23 = __floats2bfloat162_rn(v2, v3);
                if (c0 < QKV3) {
                    *(__nv_bfloat162*)(O1 + (size_t)r0 * QKV3 + c0) = p01;
                    *(__nv_bfloat162*)(O1 + (size_t)(r0 + 8) * QKV3 + c0) = p23;
                } else {
                    int cq = c0 - QKV3;
                    *(__nv_bfloat162*)(O2 + (size_t)r0 * 1536 + cq) = p01;
                    *(__nv_bfloat162*)(O2 + (size_t)(r0 + 8) * 1536 + cq) = p23;
                }
            }
        }
    } else {
        // MODE 3: plain bf16 store
#pragma unroll
        for (int mi = 0; mi < 2; mi++) {
            int r0 = m0 + wm * 32 + mi * 16 + tg;
#pragma unroll
            for (int ni = 0; ni < 8; ni++) {
                int c0 = n0 + wn * 64 + ni * 8 + (tig << 1);
                if (r0 < M)
                    *(__nv_bfloat162*)(O1 + (size_t)r0 * ldc + c0) =
                        __floats2bfloat162_rn(acc[mi][ni][0], acc[mi][ni][1]);
                if (r0 + 8 < M)
                    *(__nv_bfloat162*)(O1 + (size_t)(r0 + 8) * ldc + c0) =
                        __floats2bfloat162_rn(acc[mi][ni][2], acc[mi][ni][3]);
            }
        }
    }
}

// ---------------------------------------------------------------------------
// kv_diag / K.sum (bf16 inputs)
// ---------------------------------------------------------------------------
__global__ __launch_bounds__(256) void kvks_partial(void) {
    int c = blockIdx.x * 256 + threadIdx.x;
    int seg = blockIdx.y, b = blockIdx.z;
    const bf16* base = g_qkv + ((size_t)b * LL + seg * 196) * QKV3;
    float skv = 0.f, sks = 0.f;
#pragma unroll 4
    for (int l = 0; l < 196; l++) {
        float kk = __bfloat162float(base[(size_t)l * QKV3 + CC + c]);
        float vv = __bfloat162float(base[(size_t)l * QKV3 + 2 * CC + c]);
        skv += kk * vv;
        sks += kk;
    }
    g_pkv[(b * 16 + seg) * CC + c] = skv;
    g_pks[(b * 16 + seg) * CC + c] = sks;
}

__global__ void kvks_reduce(void) {
    int i = blockIdx.x * 256 + threadIdx.x;
    if (i >= BB * CC) return;
    int b = i / CC, c = i % CC;
    float skv = 0.f, sks = 0.f;
#pragma unroll
    for (int s = 0; s < 16; s++) {
        skv += g_pkv[(b * 16 + s) * CC + c];
        sks += g_pks[(b * 16 + s) * CC + c];
    }
    g_kv[i] = skv;
    g_ks[i] = sks;
}

__global__ __launch_bounds__(256) void zres_kernel(void) {
    int bl = blockIdx.x;
    int b = bl / LL;
    int tid = threadIdx.x;
    const bf16* qrow = g_qkv + (size_t)bl * QKV3;
    float q0 = __bfloat162float(qrow[tid]);
    float q1 = __bfloat162float(qrow[tid + 256]);
    float q2 = __bfloat162float(qrow[tid + 512]);
    const float* ks = g_ks + b * CC;
    float p = q0 * (ks[tid] + EPSF) + q1 * (ks[tid + 256] + EPSF) + q2 * (ks[tid + 512] + EPSF);
    float tot = block_sum256(p);
    float z = 1.0f / tot;
    const float* kv = g_kv + b * CC;
    bf16* outp = g_resb + (size_t)bl * CC;
    outp[tid]       = __float2bfloat16_rn(q0 * kv[tid] * z);
    outp[tid + 256] = __float2bfloat16_rn(q1 * kv[tid + 256] * z);
    outp[tid + 512] = __float2bfloat16_rn(q2 * kv[tid + 512] * z);
}

__global__ __launch_bounds__(256) void softmax_kernel(void) {
    const float* row = g_mid + (size_t)blockIdx.x * CC;
    bf16* rowo = g_midb + (size_t)blockIdx.x * CC;
    int tid = threadIdx.x;
    float v0 = row[tid], v1 = row[tid + 256], v2 = row[tid + 512];
    float m = block_max256(fmaxf(v0, fmaxf(v1, v2)));
    __syncthreads();
    float e0 = expf(v0 - m), e1 = expf(v1 - m), e2 = expf(v2 - m);
    float s = block_sum256(e0 + e1 + e2);
    float inv = 1.0f / s;
    rowo[tid]       = __float2bfloat16_rn(e0 * inv);
    rowo[tid + 256] = __float2bfloat16_rn(e1 * inv);
    rowo[tid + 512] = __float2bfloat16_rn(e2 * inv);
}

// out[b,c,l] = relu(BN(x[b,c,l] + posT[c,l] + gamma*res2b[b,l,c]))
__global__ __launch_bounds__(256) void final_kernel(const float* __restrict__ x,
                                                    const float* __restrict__ gamma,
                                                    const float* __restrict__ bw,
                                                    const float* __restrict__ bbv,
                                                    const float* __restrict__ mean,
                                                    const float* __restrict__ var,
                                                    float* __restrict__ out) {
    __shared__ float tile[32][33];
    float gm = gamma[0];
    int tx = threadIdx.x & 31, ty = threadIdx.x >> 5;
    int l0 = blockIdx.x * 32, c0 = blockIdx.y * 32, b = blockIdx.z;
#pragma unroll
    for (int i = 0; i < 4; i++) {
        int l = l0 + ty + i * 8;
        int c = c0 + tx;
        tile[tx][ty + i * 8] =
            gm * __bfloat162float(g_res2b[((size_t)b * LL + l) * CC + c]);
    }
    __syncthreads();
#pragma unroll
    for (int i = 0; i < 4; i++) {
        int c = c0 + ty + i * 8;
        int l = l0 + tx;
        float v = x[(size_t)(b * CC + c) * LL + l] + g_posT[(size_t)c * LL + l]
                  + tile[ty + i * 8][tx];
        v = (v - mean[c]) * rsqrtf(var[c] + BN_EPSF) * bw[c] + bbv[c];
        out[(size_t)(b * CC + c) * LL + l] = fmaxf(v, 0.f);
    }
}

// ---------------------------------------------------------------------------
// Launch
// ---------------------------------------------------------------------------
extern "C" void kernel_launch(void* const* d_in, const int* in_sizes, int n_in,
                              void* d_out, int out_size) {
    const float* x    = (const float*)d_in[0];
    const float* wq   = (const float*)d_in[1];
    const float* bq   = (const float*)d_in[2];
    const float* wk   = (const float*)d_in[3];
    const float* bk   = (const float*)d_in[4];
    const float* wv   = (const float*)d_in[5];
    const float* bv   = (const float*)d_in[6];
    const float* wq1  = (const float*)d_in[7];
    const float* bq1  = (const float*)d_in[8];
    const float* wk1  = (const float*)d_in[9];
    const float* bk1  = (const float*)d_in[10];
    const float* gam  = (const float*)d_in[11];
    const float* bn_w = (const float*)d_in[12];
    const float* bn_b = (const float*)d_in[13];
    const float* bn_m = (const float*)d_in[14];
    const float* bn_v = (const float*)d_in[15];
    const float* pw   = (const float*)d_in[16];
    const float* pb   = (const float*)d_in[17];
    float* out = (float*)d_out;

    float *p_bcat, *p_mid;
    bf16 *p_tb, *p_wcatb, *p_qkv, *p_qk1, *p_resb, *p_midb, *p_res2b;
    cudaGetSymbolAddress((void**)&p_bcat,  g_bcat);
    cudaGetSymbolAddress((void**)&p_mid,   g_mid);
    cudaGetSymbolAddress((void**)&p_tb,    g_tb);
    cudaGetSymbolAddress((void**)&p_wcatb, g_wcatb);
    cudaGetSymbolAddress((void**)&p_qkv,   g_qkv);
    cudaGetSymbolAddress((void**)&p_qk1,   g_qk1);
    cudaGetSymbolAddress((void**)&p_resb,  g_resb);
    cudaGetSymbolAddress((void**)&p_midb,  g_midb);
    cudaGetSymbolAddress((void**)&p_res2b, g_res2b);

    pe_kernel<<<(LL * 64 + 255) / 256, 256>>>();
    pos_kernel<<<LL, 256>>>(pw, pb);
    posT_kernel<<<dim3(LL / 32, CC / 32), 256>>>();
    wcat_kernel<<<(CC * NCAT + 255) / 256, 256>>>(wq, wk, wv, wq1, wk1,
                                                  bq, bk, bv, bq1, bk1);
    addpos_kernel<<<dim3(LL / 32, CC / 32, BB), 256>>>(x);

    // gemm1: projection, bf16 epilogue split Q,K,V / Q1,K1
    gemm_bf<false, 1><<<dim3(NCAT / 128, (BB * LL) / 128, 1), 256>>>(
        p_tb, CC, 0, p_wcatb, NCAT, 0,
        nullptr, 0, 0, BB * LL, CC,
        p_bcat, p_qkv, p_qk1);

    kvks_partial<<<dim3(CC / 256, 16, BB), 256>>>();
    kvks_reduce<<<(BB * CC + 255) / 256, 256>>>();
    zres_kernel<<<BB * LL, 256>>>();

    // gemm2: mid = Q1^T @ K1 per batch
    gemm_bf<true, 0><<<dim3(CC / 128, CC / 128, BB), 256>>>(
        p_qk1, 1536, (size_t)LL * 1536,
        p_qk1 + 768, 1536, (size_t)LL * 1536,
        p_mid, CC, (size_t)CC * CC, CC, LL,
        nullptr, nullptr, nullptr);

    softmax_kernel<<<BB * CC, 256>>>();

    // gemm3: res2 (bf16) = res1 @ mid per batch
    gemm_bf<false, 3><<<dim3(CC / 128, (LL + 127) / 128, BB), 256>>>(
        p_resb, CC, (size_t)LL * CC,
        p_midb, CC, (size_t)CC * CC,
        nullptr, CC, (size_t)LL * CC, LL, CC,
        nullptr, p_res2b, nullptr);

    // final: BN + ReLU + transpose back to NCHW
    final_kernel<<<dim3(LL / 32, CC / 32, BB), 256>>>(x, gam, bn_w, bn_b, bn_m, bn_v, out);
}

// round 10
// speedup vs baseline: 1.0991x; 1.0340x over previous
#include <cuda_runtime.h>
#include <cuda_bf16.h>
#include <math.h>
#include <stdint.h>

#define BB   8
#define CC   768
#define HH   56
#define LL   3136
#define NCAT 3840
#define QKV3 2304
#define EPSF 1e-6f
#define BN_EPSF 1e-5f

typedef __nv_bfloat16 bf16;

// ---------------------------------------------------------------------------
// Scratch (device globals; no allocations allowed)
// ---------------------------------------------------------------------------
static __device__ __align__(16) float g_pe[LL * 64];
static __device__ __align__(16) float g_pos[LL * CC];      // [l][c]
static __device__ __align__(16) float g_posT[CC * LL];     // [c][l]
static __device__ __align__(16) bf16  g_wcatb[CC * NCAT];  // [k][n]
static __device__ __align__(16) float g_bcat[NCAT];
static __device__ __align__(16) bf16  g_tb[(size_t)BB * LL * CC];
static __device__ __align__(16) bf16  g_qkv[(size_t)BB * LL * QKV3];
static __device__ __align__(16) bf16  g_qk1[(size_t)BB * LL * 1536];
static __device__ __align__(16) float g_pkv[BB * 16 * CC];
static __device__ __align__(16) float g_pks[BB * 16 * CC];
static __device__ __align__(16) float g_kv[BB * CC];
static __device__ __align__(16) float g_ks[BB * CC];
static __device__ __align__(16) bf16  g_resb[(size_t)BB * LL * CC];
static __device__ __align__(16) float g_mid[(size_t)BB * CC * CC];
static __device__ __align__(16) bf16  g_midb[(size_t)BB * CC * CC];
static __device__ __align__(16) bf16  g_res2b[(size_t)BB * LL * CC];

// ---------------------------------------------------------------------------
// PTX helpers (sm_100 baseline only — NO tcgen05)
// ---------------------------------------------------------------------------
__device__ __forceinline__ void mma_bf16(float* d, const uint32_t* a, const uint32_t* b) {
    asm volatile(
        "mma.sync.aligned.m16n8k16.row.col.f32.bf16.bf16.f32 "
        "{%0,%1,%2,%3}, {%4,%5,%6,%7}, {%8,%9}, {%0,%1,%2,%3};\n"
        : "+f"(d[0]), "+f"(d[1]), "+f"(d[2]), "+f"(d[3])
        : "r"(a[0]), "r"(a[1]), "r"(a[2]), "r"(a[3]), "r"(b[0]), "r"(b[1]));
}
__device__ __forceinline__ void ldsm_x4(uint32_t* r, uint32_t addr) {
    asm volatile("ldmatrix.sync.aligned.m8n8.x4.shared.b16 {%0,%1,%2,%3}, [%4];\n"
                 : "=r"(r[0]), "=r"(r[1]), "=r"(r[2]), "=r"(r[3]) : "r"(addr));
}
__device__ __forceinline__ void ldsm_x4t(uint32_t* r, uint32_t addr) {
    asm volatile("ldmatrix.sync.aligned.m8n8.x4.trans.shared.b16 {%0,%1,%2,%3}, [%4];\n"
                 : "=r"(r[0]), "=r"(r[1]), "=r"(r[2]), "=r"(r[3]) : "r"(addr));
}
__device__ __forceinline__ void cp16(void* s, const void* g, bool p) {
    uint32_t sa = (uint32_t)__cvta_generic_to_shared(s);
    int sz = p ? 16 : 0;
    asm volatile("cp.async.cg.shared.global [%0], [%1], 16, %2;\n" :: "r"(sa), "l"(g), "r"(sz));
}
__device__ __forceinline__ void cp_commit() { asm volatile("cp.async.commit_group;\n"); }
template <int N>
__device__ __forceinline__ void cp_wait() { asm volatile("cp.async.wait_group %0;\n" :: "n"(N)); }

// ---------------------------------------------------------------------------
// Reductions
// ---------------------------------------------------------------------------
__device__ __forceinline__ float block_sum256(float v) {
    __shared__ float sm[8];
    int lane = threadIdx.x & 31, w = threadIdx.x >> 5;
#pragma unroll
    for (int o = 16; o; o >>= 1) v += __shfl_xor_sync(0xffffffffu, v, o);
    if (lane == 0) sm[w] = v;
    __syncthreads();
    float t = sm[lane & 7];
#pragma unroll
    for (int o = 4; o; o >>= 1) t += __shfl_xor_sync(0xffffffffu, t, o);
    return t;
}
__device__ __forceinline__ float block_max256(float v) {
    __shared__ float sm[8];
    int lane = threadIdx.x & 31, w = threadIdx.x >> 5;
#pragma unroll
    for (int o = 16; o; o >>= 1) v = fmaxf(v, __shfl_xor_sync(0xffffffffu, v, o));
    if (lane == 0) sm[w] = v;
    __syncthreads();
    float t = sm[lane & 7];
#pragma unroll
    for (int o = 4; o; o >>= 1) t = fmaxf(t, __shfl_xor_sync(0xffffffffu, t, o));
    return t;
}

// ---------------------------------------------------------------------------
// Pre-kernels
// ---------------------------------------------------------------------------
__global__ void pe_kernel(void) {
    int idx = blockIdx.x * 256 + threadIdx.x;
    if (idx >= LL * 64) return;
    int l = idx >> 6, k = idx & 63;
    int kk = k & 31;
    float coord = (k < 32) ? (float)(l / HH + 1) : (float)(l % HH + 1);
    float v = coord / ((float)HH + EPSF) * 6.283185307179586f;
    float dt = powf(10000.0f, (float)(kk & ~1) / 32.0f);
    float p = v / dt;
    g_pe[idx] = (kk & 1) ? cosf(p) : sinf(p);
}

__global__ __launch_bounds__(256) void pos_kernel(const float* __restrict__ pw,
                                                  const float* __restrict__ pb) {
    __shared__ float pe_s[64];
    int l = blockIdx.x, tid = threadIdx.x;
    if (tid < 64) pe_s[tid] = g_pe[l * 64 + tid];
    __syncthreads();
#pragma unroll
    for (int j = 0; j < 3; j++) {
        int c = tid + j * 256;
        float acc = pb[c];
#pragma unroll 16
        for (int k = 0; k < 64; k++) acc += pe_s[k] * pw[k * CC + c];
        g_pos[(size_t)l * CC + c] = acc;
    }
}

// posT[c][l] = pos[l][c]
__global__ __launch_bounds__(256) void posT_kernel(void) {
    __shared__ float tile[32][33];
    int tx = threadIdx.x & 31, ty = threadIdx.x >> 5;
    int l0 = blockIdx.x * 32, c0 = blockIdx.y * 32;
#pragma unroll
    for (int i = 0; i < 4; i++)
        tile[ty + i * 8][tx] = g_pos[(size_t)(l0 + ty + i * 8) * CC + c0 + tx];
    __syncthreads();
#pragma unroll
    for (int i = 0; i < 4; i++)
        g_posT[(size_t)(c0 + ty + i * 8) * LL + l0 + tx] = tile[tx][ty + i * 8];
}

// Weights -> bf16 [k][n], biases fp32
__global__ void wcat_kernel(const float* __restrict__ wq, const float* __restrict__ wk,
                            const float* __restrict__ wv, const float* __restrict__ wq1,
                            const float* __restrict__ wk1,
                            const float* __restrict__ bq, const float* __restrict__ bk,
                            const float* __restrict__ bv, const float* __restrict__ bq1,
                            const float* __restrict__ bk1) {
    int idx = blockIdx.x * 256 + threadIdx.x;
    if (idx < NCAT) {
        int g = idx / CC, c = idx % CC;
        const float* bp = (g == 0) ? bq : (g == 1) ? bk : (g == 2) ? bv : (g == 3) ? bq1 : bk1;
        g_bcat[idx] = bp[c];
    }
    if (idx >= CC * NCAT) return;
    int k = idx / NCAT, n = idx % NCAT;
    int g = n / CC, c = n % CC;
    const float* wp = (g == 0) ? wq : (g == 1) ? wk : (g == 2) ? wv : (g == 3) ? wq1 : wk1;
    g_wcatb[idx] = __float2bfloat16_rn(wp[k * CC + c]);
}

// t_bf16[b,l,c] = bf16(x[b,c,l] + pos[l,c])
__global__ __launch_bounds__(256) void addpos_kernel(const float* __restrict__ x) {
    __shared__ float tile[32][33];
    int tx = threadIdx.x & 31, ty = threadIdx.x >> 5;
    int l0 = blockIdx.x * 32, c0 = blockIdx.y * 32, b = blockIdx.z;
#pragma unroll
    for (int i = 0; i < 4; i++) {
        int c = c0 + ty + i * 8;
        tile[ty + i * 8][tx] = x[(size_t)(b * CC + c) * LL + l0 + tx];
    }
    __syncthreads();
#pragma unroll
    for (int i = 0; i < 4; i++) {
        int l = l0 + ty + i * 8;
        int c = c0 + tx;
        g_tb[((size_t)b * LL + l) * CC + c] =
            __float2bfloat16_rn(tile[tx][ty + i * 8] + g_pos[(size_t)l * CC + c]);
    }
}

// ---------------------------------------------------------------------------
// bf16 tensor-core GEMM. BM=BN=128, BK=32, 256 threads, warp tile 32x64.
// 3-stage cp.async pipeline (dynamic smem), ONE __syncthreads per K-iter.
// MODE 0: fp32 C store (gemm2).
// MODE 1: projection epilogue — +bias, ReLU n<1536; bf16 to qkv/qk1 (gemm1).
// MODE 3: plain bf16 store to O1, ld = ldc (gemm3 -> res2 bf16).
// ---------------------------------------------------------------------------
template <bool TRANSA, int MODE>
__global__ __launch_bounds__(256) void gemm_bf(
    const bf16* __restrict__ A, int lda, size_t sA,
    const bf16* __restrict__ B, int ldb, size_t sB,
    float* __restrict__ C, int ldc, size_t sC, int M, int K,
    const float* __restrict__ bias, bf16* __restrict__ O1, bf16* __restrict__ O2)
{
    constexpr int ASZ = TRANSA ? 32 * 136 : 128 * 40;   // elems per A stage
    constexpr int BSZ = 32 * 136;                        // elems per B stage
    extern __shared__ __align__(16) bf16 sdyn[];
    bf16* const Abase = sdyn;                // 3 stages of A
    bf16* const Bbase = sdyn + 3 * ASZ;      // 3 stages of B

    A += (size_t)blockIdx.z * sA;
    B += (size_t)blockIdx.z * sB;
    if (MODE == 0) C += (size_t)blockIdx.z * sC;
    if (MODE == 3) O1 += (size_t)blockIdx.z * sC;

    const int tid = threadIdx.x;
    const int m0 = blockIdx.y * 128, n0 = blockIdx.x * 128;
    const int lane = tid & 31, wid = tid >> 5;
    const int wm = wid >> 1, wn = wid & 1;
    const int tg = lane >> 2, tig = lane & 3;

    auto load_tiles = [&](int buf, int kb) {
        bf16* As = Abase + buf * ASZ;
        bf16* Bs = Bbase + buf * BSZ;
#pragma unroll
        for (int i = 0; i < 2; i++) {
            int f = tid + i * 256;
            if (!TRANSA) {
                int row = f >> 2, c8 = (f & 3) << 3;
                bool p = (m0 + row) < M;
                const bf16* g = A + (size_t)(p ? (m0 + row) : 0) * lda + kb + c8;
                cp16(&As[row * 40 + c8], g, p);
            } else {
                int row = f >> 4, c8 = (f & 15) << 3;
                const bf16* g = A + (size_t)(kb + row) * lda + m0 + c8;
                cp16(&As[row * 136 + c8], g, true);
            }
        }
#pragma unroll
        for (int i = 0; i < 2; i++) {
            int f = tid + i * 256;
            int row = f >> 4, c8 = (f & 15) << 3;
            const bf16* g = B + (size_t)(kb + row) * ldb + n0 + c8;
            cp16(&Bs[row * 136 + c8], g, true);
        }
        cp_commit();
    };

    float acc[2][8][4];
#pragma unroll
    for (int mi = 0; mi < 2; mi++)
#pragma unroll
        for (int ni = 0; ni < 8; ni++)
#pragma unroll
            for (int r = 0; r < 4; r++) acc[mi][ni][r] = 0.0f;

    int a_off[2], b_off;
    if (!TRANSA) {
#pragma unroll
        for (int mi = 0; mi < 2; mi++)
            a_off[mi] = (wm * 32 + mi * 16 + (lane & 15)) * 40 + ((lane >> 4) << 3);
    } else {
#pragma unroll
        for (int mi = 0; mi < 2; mi++)
            a_off[mi] = (((lane >> 4) & 1) * 8 + (lane & 7)) * 136
                        + wm * 32 + mi * 16 + ((lane >> 3) & 1) * 8;
    }
    b_off = (((lane >> 3) & 1) * 8 + (lane & 7)) * 136
            + wn * 64 + ((lane >> 4) & 1) * 8;

    const int nk = K >> 5;
    load_tiles(0, 0);
    load_tiles(1, 32);

    int buf = 0;
    for (int it = 0; it < nk; it++) {
        if (it + 1 < nk) cp_wait<1>(); else cp_wait<0>();
        __syncthreads();
        if (it + 2 < nk) {
            int nbuf = buf + 2; if (nbuf >= 3) nbuf -= 3;
            load_tiles(nbuf, (it + 2) << 5);
        }

        uint32_t abase = (uint32_t)__cvta_generic_to_shared(Abase + buf * ASZ);
        uint32_t bbase = (uint32_t)__cvta_generic_to_shared(Bbase + buf * BSZ);
#pragma unroll
        for (int kk = 0; kk < 32; kk += 16) {
            uint32_t af[2][4];
#pragma unroll
            for (int mi = 0; mi < 2; mi++) {
                uint32_t ad;
                if (!TRANSA) ad = abase + (uint32_t)(a_off[mi] + kk) * 2;
                else         ad = abase + (uint32_t)(a_off[mi] + kk * 136) * 2;
                if (!TRANSA) ldsm_x4(af[mi], ad);
                else         ldsm_x4t(af[mi], ad);
            }
            uint32_t bfr[8][2];
#pragma unroll
            for (int ni2 = 0; ni2 < 4; ni2++) {
                uint32_t r[4];
                uint32_t bd = bbase + (uint32_t)(b_off + kk * 136 + ni2 * 16) * 2;
                ldsm_x4t(r, bd);
                bfr[2 * ni2][0] = r[0]; bfr[2 * ni2][1] = r[1];
                bfr[2 * ni2 + 1][0] = r[2]; bfr[2 * ni2 + 1][1] = r[3];
            }
#pragma unroll
            for (int mi = 0; mi < 2; mi++)
#pragma unroll
                for (int ni = 0; ni < 8; ni++)
                    mma_bf16(acc[mi][ni], af[mi], bfr[ni]);
        }
        buf++; if (buf == 3) buf = 0;
    }

    if (MODE == 0) {
#pragma unroll
        for (int mi = 0; mi < 2; mi++) {
            int r0 = m0 + wm * 32 + mi * 16 + tg;
#pragma unroll
            for (int ni = 0; ni < 8; ni++) {
                int c0 = n0 + wn * 64 + ni * 8 + (tig << 1);
                if (r0 < M)
                    *(float2*)(C + (size_t)r0 * ldc + c0) =
                        make_float2(acc[mi][ni][0], acc[mi][ni][1]);
                if (r0 + 8 < M)
                    *(float2*)(C + (size_t)(r0 + 8) * ldc + c0) =
                        make_float2(acc[mi][ni][2], acc[mi][ni][3]);
            }
        }
    } else if (MODE == 1) {
#pragma unroll
        for (int mi = 0; mi < 2; mi++) {
            int r0 = m0 + wm * 32 + mi * 16 + tg;
#pragma unroll
            for (int ni = 0; ni < 8; ni++) {
                int c0 = n0 + wn * 64 + ni * 8 + (tig << 1);
                float2 bb = *(const float2*)(bias + c0);
                float v0 = acc[mi][ni][0] + bb.x, v1 = acc[mi][ni][1] + bb.y;
                float v2 = acc[mi][ni][2] + bb.x, v3 = acc[mi][ni][3] + bb.y;
                if (c0 < 1536) {
                    v0 = fmaxf(v0, 0.f); v1 = fmaxf(v1, 0.f);
                    v2 = fmaxf(v2, 0.f); v3 = fmaxf(v3, 0.f);
                }
                __nv_bfloat162 p01 = __floats2bfloat162_rn(v0, v1);
                __nv_bfloat162 p23 = __floats2bfloat162_rn(v2, v3);
                if (c0 < QKV3) {
                    *(__nv_bfloat162*)(O1 + (size_t)r0 * QKV3 + c0) = p01;
                    *(__nv_bfloat162*)(O1 + (size_t)(r0 + 8) * QKV3 + c0) = p23;
                } else {
                    int cq = c0 - QKV3;
                    *(__nv_bfloat162*)(O2 + (size_t)r0 * 1536 + cq) = p01;
                    *(__nv_bfloat162*)(O2 + (size_t)(r0 + 8) * 1536 + cq) = p23;
                }
            }
        }
    } else {
#pragma unroll
        for (int mi = 0; mi < 2; mi++) {
            int r0 = m0 + wm * 32 + mi * 16 + tg;
#pragma unroll
            for (int ni = 0; ni < 8; ni++) {
                int c0 = n0 + wn * 64 + ni * 8 + (tig << 1);
                if (r0 < M)
                    *(__nv_bfloat162*)(O1 + (size_t)r0 * ldc + c0) =
                        __floats2bfloat162_rn(acc[mi][ni][0], acc[mi][ni][1]);
                if (r0 + 8 < M)
                    *(__nv_bfloat162*)(O1 + (size_t)(r0 + 8) * ldc + c0) =
                        __floats2bfloat162_rn(acc[mi][ni][2], acc[mi][ni][3]);
            }
        }
    }
}

// ---------------------------------------------------------------------------
// kv_diag / K.sum (bf16 inputs)
// ---------------------------------------------------------------------------
__global__ __launch_bounds__(256) void kvks_partial(void) {
    int c = blockIdx.x * 256 + threadIdx.x;
    int seg = blockIdx.y, b = blockIdx.z;
    const bf16* base = g_qkv + ((size_t)b * LL + seg * 196) * QKV3;
    float skv = 0.f, sks = 0.f;
#pragma unroll 4
    for (int l = 0; l < 196; l++) {
        float kk = __bfloat162float(base[(size_t)l * QKV3 + CC + c]);
        float vv = __bfloat162float(base[(size_t)l * QKV3 + 2 * CC + c]);
        skv += kk * vv;
        sks += kk;
    }
    g_pkv[(b * 16 + seg) * CC + c] = skv;
    g_pks[(b * 16 + seg) * CC + c] = sks;
}

__global__ void kvks_reduce(void) {
    int i = blockIdx.x * 256 + threadIdx.x;
    if (i >= BB * CC) return;
    int b = i / CC, c = i % CC;
    float skv = 0.f, sks = 0.f;
#pragma unroll
    for (int s = 0; s < 16; s++) {
        skv += g_pkv[(b * 16 + s) * CC + c];
        sks += g_pks[(b * 16 + s) * CC + c];
    }
    g_kv[i] = skv;
    g_ks[i] = sks;
}

__global__ __launch_bounds__(256) void zres_kernel(void) {
    int bl = blockIdx.x;
    int b = bl / LL;
    int tid = threadIdx.x;
    const bf16* qrow = g_qkv + (size_t)bl * QKV3;
    float q0 = __bfloat162float(qrow[tid]);
    float q1 = __bfloat162float(qrow[tid + 256]);
    float q2 = __bfloat162float(qrow[tid + 512]);
    const float* ks = g_ks + b * CC;
    float p = q0 * (ks[tid] + EPSF) + q1 * (ks[tid + 256] + EPSF) + q2 * (ks[tid + 512] + EPSF);
    float tot = block_sum256(p);
    float z = 1.0f / tot;
    const float* kv = g_kv + b * CC;
    bf16* outp = g_resb + (size_t)bl * CC;
    outp[tid]       = __float2bfloat16_rn(q0 * kv[tid] * z);
    outp[tid + 256] = __float2bfloat16_rn(q1 * kv[tid + 256] * z);
    outp[tid + 512] = __float2bfloat16_rn(q2 * kv[tid + 512] * z);
}

__global__ __launch_bounds__(256) void softmax_kernel(void) {
    const float* row = g_mid + (size_t)blockIdx.x * CC;
    bf16* rowo = g_midb + (size_t)blockIdx.x * CC;
    int tid = threadIdx.x;
    float v0 = row[tid], v1 = row[tid + 256], v2 = row[tid + 512];
    float m = block_max256(fmaxf(v0, fmaxf(v1, v2)));
    __syncthreads();
    float e0 = expf(v0 - m), e1 = expf(v1 - m), e2 = expf(v2 - m);
    float s = block_sum256(e0 + e1 + e2);
    float inv = 1.0f / s;
    rowo[tid]       = __float2bfloat16_rn(e0 * inv);
    rowo[tid + 256] = __float2bfloat16_rn(e1 * inv);
    rowo[tid + 512] = __float2bfloat16_rn(e2 * inv);
}

// out[b,c,l] = relu(BN(x[b,c,l] + posT[c,l] + gamma*res2b[b,l,c]))
__global__ __launch_bounds__(256) void final_kernel(const float* __restrict__ x,
                                                    const float* __restrict__ gamma,
                                                    const float* __restrict__ bw,
                                                    const float* __restrict__ bbv,
                                                    const float* __restrict__ mean,
                                                    const float* __restrict__ var,
                                                    float* __restrict__ out) {
    __shared__ float tile[32][33];
    float gm = gamma[0];
    int tx = threadIdx.x & 31, ty = threadIdx.x >> 5;
    int l0 = blockIdx.x * 32, c0 = blockIdx.y * 32, b = blockIdx.z;
#pragma unroll
    for (int i = 0; i < 4; i++) {
        int l = l0 + ty + i * 8;
        int c = c0 + tx;
        tile[tx][ty + i * 8] =
            gm * __bfloat162float(g_res2b[((size_t)b * LL + l) * CC + c]);
    }
    __syncthreads();
#pragma unroll
    for (int i = 0; i < 4; i++) {
        int c = c0 + ty + i * 8;
        int l = l0 + tx;
        float v = x[(size_t)(b * CC + c) * LL + l] + g_posT[(size_t)c * LL + l]
                  + tile[ty + i * 8][tx];
        v = (v - mean[c]) * rsqrtf(var[c] + BN_EPSF) * bw[c] + bbv[c];
        out[(size_t)(b * CC + c) * LL + l] = fmaxf(v, 0.f);
    }
}

// ---------------------------------------------------------------------------
// Launch
// ---------------------------------------------------------------------------
extern "C" void kernel_launch(void* const* d_in, const int* in_sizes, int n_in,
                              void* d_out, int out_size) {
    const float* x    = (const float*)d_in[0];
    const float* wq   = (const float*)d_in[1];
    const float* bq   = (const float*)d_in[2];
    const float* wk   = (const float*)d_in[3];
    const float* bk   = (const float*)d_in[4];
    const float* wv   = (const float*)d_in[5];
    const float* bv   = (const float*)d_in[6];
    const float* wq1  = (const float*)d_in[7];
    const float* bq1  = (const float*)d_in[8];
    const float* wk1  = (const float*)d_in[9];
    const float* bk1  = (const float*)d_in[10];
    const float* gam  = (const float*)d_in[11];
    const float* bn_w = (const float*)d_in[12];
    const float* bn_b = (const float*)d_in[13];
    const float* bn_m = (const float*)d_in[14];
    const float* bn_v = (const float*)d_in[15];
    const float* pw   = (const float*)d_in[16];
    const float* pb   = (const float*)d_in[17];
    float* out = (float*)d_out;

    float *p_bcat, *p_mid;
    bf16 *p_tb, *p_wcatb, *p_qkv, *p_qk1, *p_resb, *p_midb, *p_res2b;
    cudaGetSymbolAddress((void**)&p_bcat,  g_bcat);
    cudaGetSymbolAddress((void**)&p_mid,   g_mid);
    cudaGetSymbolAddress((void**)&p_tb,    g_tb);
    cudaGetSymbolAddress((void**)&p_wcatb, g_wcatb);
    cudaGetSymbolAddress((void**)&p_qkv,   g_qkv);
    cudaGetSymbolAddress((void**)&p_qk1,   g_qk1);
    cudaGetSymbolAddress((void**)&p_resb,  g_resb);
    cudaGetSymbolAddress((void**)&p_midb,  g_midb);
    cudaGetSymbolAddress((void**)&p_res2b, g_res2b);

    // Dynamic smem sizes (3-stage): non-trans 56832 B, trans 52224 B
    const int SMEM_NT = 3 * (128 * 40 + 32 * 136) * 2;
    const int SMEM_T  = 3 * (32 * 136 + 32 * 136) * 2;
    cudaFuncSetAttribute(gemm_bf<false, 1>,
                         cudaFuncAttributeMaxDynamicSharedMemorySize, SMEM_NT);
    cudaFuncSetAttribute(gemm_bf<true, 0>,
                         cudaFuncAttributeMaxDynamicSharedMemorySize, SMEM_T);
    cudaFuncSetAttribute(gemm_bf<false, 3>,
                         cudaFuncAttributeMaxDynamicSharedMemorySize, SMEM_NT);

    pe_kernel<<<(LL * 64 + 255) / 256, 256>>>();
    pos_kernel<<<LL, 256>>>(pw, pb);
    posT_kernel<<<dim3(LL / 32, CC / 32), 256>>>();
    wcat_kernel<<<(CC * NCAT + 255) / 256, 256>>>(wq, wk, wv, wq1, wk1,
                                                  bq, bk, bv, bq1, bk1);
    addpos_kernel<<<dim3(LL / 32, CC / 32, BB), 256>>>(x);

    // gemm1: projection, bf16 epilogue split Q,K,V / Q1,K1
    gemm_bf<false, 1><<<dim3(NCAT / 128, (BB * LL) / 128, 1), 256, SMEM_NT>>>(
        p_tb, CC, 0, p_wcatb, NCAT, 0,
        nullptr, 0, 0, BB * LL, CC,
        p_bcat, p_qkv, p_qk1);

    kvks_partial<<<dim3(CC / 256, 16, BB), 256>>>();
    kvks_reduce<<<(BB * CC + 255) / 256, 256>>>();
    zres_kernel<<<BB * LL, 256>>>();

    // gemm2: mid = Q1^T @ K1 per batch
    gemm_bf<true, 0><<<dim3(CC / 128, CC / 128, BB), 256, SMEM_T>>>(
        p_qk1, 1536, (size_t)LL * 1536,
        p_qk1 + 768, 1536, (size_t)LL * 1536,
        p_mid, CC, (size_t)CC * CC, CC, LL,
        nullptr, nullptr, nullptr);

    softmax_kernel<<<BB * CC, 256>>>();

    // gemm3: res2 (bf16) = res1 @ mid per batch
    gemm_bf<false, 3><<<dim3(CC / 128, (LL + 127) / 128, BB), 256, SMEM_NT>>>(
        p_resb, CC, (size_t)LL * CC,
        p_midb, CC, (size_t)CC * CC,
        nullptr, CC, (size_t)LL * CC, LL, CC,
        nullptr, p_res2b, nullptr);

    // final: BN + ReLU + transpose back to NCHW
    final_kernel<<<dim3(LL / 32, CC / 32, BB), 256>>>(x, gam, bn_w, bn_b, bn_m, bn_v, out);
}